// round 5
// baseline (speedup 1.0000x reference)
#include <cuda_runtime.h>
#include <math.h>

// ---------------- static config ----------------
constexpr int NXg = 432, NYg = 496, Bb = 4;
constexpr int Hh = 248, Ww = 216;
constexpr int HW = Hh * Ww;            // 53568
constexpr int C_IN = 384, NDF = 16;
constexpr int NYNX = NYg * NXg;        // 214272
constexpr int KS = 15, RR = 7;
constexpr float BN_EPS = 1e-3f;
constexpr int CNT = Bb * HW;           // 214272
constexpr int PL4 = HW / 4;            // 13392

constexpr int TW = 14, TH = 16;        // 16x16 tiles over 248x216
constexpr int NB1 = TW * TH * Bb;      // 896 tile blocks

// concat-copy layout (float4 units)
constexpr int SP4 = C_IN * PL4;        // 5,142,528 spatial float4 / batch
constexpr int BP4 = (C_IN + NDF) * PL4;// 5,356,800 out float4 / batch
constexpr int NCP = Bb * SP4;          // 20,570,112 total copy float4
constexpr int CPB = 1024;              // float4 per copy block (256 thr x 4)
// copy-block quotas per launch (sum = NCP / CPB = 20088)
constexpr int CP_INIT = 3000, CP_HIST = 3000, CP_BLUR = 3500, CP_RES = 3500,
              CP_S1 = 1500, CP_CONV2 = 4000, CP_S2 = 1588;
constexpr int ST_INIT = 0;
constexpr int ST_HIST = ST_INIT + CP_INIT;   // 3000
constexpr int ST_BLUR = ST_HIST + CP_HIST;   // 6000
constexpr int ST_RES  = ST_BLUR + CP_BLUR;   // 9500
constexpr int ST_S1   = ST_RES + CP_RES;     // 13000
constexpr int ST_CONV2= ST_S1 + CP_S1;       // 14500
constexpr int ST_S2   = ST_CONV2 + CP_CONV2; // 18500
static_assert(ST_S2 + CP_S2 == NCP / CPB, "quota sum");

// ---------------- scratch (static, no allocation) ----------------
__device__ int   d_hist[Bb * NYNX];
__device__ float d_dm  [Bb * NYNX];
__device__ int   d_max [Bb];
__device__ float d_gauss[KS];
__device__ float d_buf1[Bb * 8  * HW];
__device__ float d_buf2[Bb * 16 * HW];
__device__ float d_part1[16 * NB1];
__device__ float d_part2[32 * NB1];
__device__ float d_sc1[8],  d_sh1[8];
__device__ float d_sc2[16], d_sh2[16];

// copy one 1024-float4 chunk of the spatial passthrough, MLP=4 (front-batched)
__device__ __forceinline__ void copy_chunk(int globalBlk,
                                           const float4* __restrict__ sp,
                                           float4* __restrict__ out) {
    int base = globalBlk * CPB + (int)threadIdx.x;
    int j0 = base, j1 = base + 256, j2 = base + 512, j3 = base + 768;
    float4 v0 = sp[j0];
    float4 v1 = sp[j1];
    float4 v2 = sp[j2];
    float4 v3 = sp[j3];
    int b0 = j0 / SP4, b1 = j1 / SP4, b2 = j2 / SP4, b3 = j3 / SP4;
    out[b0 * BP4 + (j0 - b0 * SP4)] = v0;
    out[b1 * BP4 + (j1 - b1 * SP4)] = v1;
    out[b2 * BP4 + (j2 - b2 * SP4)] = v2;
    out[b3 * BP4 + (j3 - b3 * SP4)] = v3;
}

// ---------------- kernels ----------------
__global__ void k_init(const float4* __restrict__ sp, float4* __restrict__ out) {
    if (blockIdx.x >= 512) {
        copy_chunk(ST_INIT + (int)blockIdx.x - 512, sp, out);
        return;
    }
    int i = blockIdx.x * blockDim.x + threadIdx.x;
    int stride = 512 * blockDim.x;
    for (int p = i; p < Bb * NYNX; p += stride) d_hist[p] = 0;
    if (i < Bb) d_max[i] = 0;
    if (i == 0) {
        float g[KS]; float s = 0.f;
        #pragma unroll
        for (int k = 0; k < KS; k++) {
            float c = (float)(k - RR);
            g[k] = expf(-(c * c) / 78.125f);   // 2*sigma^2, sigma=6.25
            s += g[k];
        }
        #pragma unroll
        for (int k = 0; k < KS; k++) d_gauss[k] = g[k] / s;
    }
}

__global__ void k_hist(const float* __restrict__ pts, int n, int workBlocks,
                       const float4* __restrict__ sp, float4* __restrict__ out) {
    if ((int)blockIdx.x >= workBlocks) {
        copy_chunk(ST_HIST + (int)blockIdx.x - workBlocks, sp, out);
        return;
    }
    int i = blockIdx.x * blockDim.x + threadIdx.x;
    if (i >= n) return;
    float b_f = pts[i * 5 + 0];
    float px  = pts[i * 5 + 1];
    float py  = pts[i * 5 + 2];
    int b  = (int)b_f;
    int xi = (int)__fdiv_rn(px - 0.0f, 0.16f);      // exact f32 division semantics
    int yi = (int)__fdiv_rn(py - (-39.68f), 0.16f);
    xi = min(max(xi, 0), NXg - 1);
    yi = min(max(yi, 0), NYg - 1);
    atomicAdd(&d_hist[b * NYNX + yi * NXg + xi], 1);
}

// fused separable 15-tap gaussian blur (zero pad) + per-batch max
// flattened grid: 896 tile blocks (14 x 16 x 4), then copy blocks
__global__ __launch_bounds__(256) void k_blur(const float4* __restrict__ sp,
                                              float4* __restrict__ out) {
    if (blockIdx.x >= (unsigned)(14 * 16 * Bb)) {
        copy_chunk(ST_BLUR + (int)blockIdx.x - 14 * 16 * Bb, sp, out);
        return;
    }
    __shared__ float a[46][48];
    __shared__ float v[32][48];
    __shared__ float g[KS];
    __shared__ float red[256];
    int wid = blockIdx.x;
    int bx = wid % 14, by = (wid / 14) % 16, b = wid / (14 * 16);
    int x0 = bx * 32, y0 = by * 32;
    int tid = threadIdx.x;
    if (tid < KS) g[tid] = d_gauss[tid];
    const int* h = d_hist + b * NYNX;
    for (int i = tid; i < 46 * 46; i += 256) {
        int ly = i / 46, lx = i - ly * 46;
        int gy = y0 - 7 + ly, gx = x0 - 7 + lx;
        a[ly][lx] = (gy >= 0 && gy < NYg && gx >= 0 && gx < NXg)
                        ? (float)h[gy * NXg + gx] : 0.f;
    }
    __syncthreads();
    for (int i = tid; i < 32 * 46; i += 256) {
        int ly = i / 46, lx = i - ly * 46;
        float acc = 0.f;
        #pragma unroll
        for (int j = 0; j < KS; j++) acc = fmaf(g[j], a[ly + j][lx], acc);
        v[ly][lx] = acc;
    }
    __syncthreads();
    float m = 0.f;
    for (int i = tid; i < 32 * 32; i += 256) {
        int ly = i / 32, lx = i - ly * 32;
        int gy = y0 + ly, gx = x0 + lx;
        if (gy < NYg && gx < NXg) {
            float acc = 0.f;
            #pragma unroll
            for (int j = 0; j < KS; j++) acc = fmaf(g[j], v[ly][lx + j], acc);
            d_dm[b * NYNX + gy * NXg + gx] = acc;
            m = fmaxf(m, acc);
        }
    }
    red[tid] = m;
    __syncthreads();
    for (int s = 128; s > 0; s >>= 1) {
        if (tid < s) red[tid] = fmaxf(red[tid], red[tid + s]);
        __syncthreads();
    }
    if (tid == 0) atomicMax(&d_max[b], __float_as_int(red[0]));  // vals >= 0
}

// fused: antialiased 2x resize (+ /max) -> conv3x3 1->8 -> BN1 partial stats
__global__ __launch_bounds__(256) void k_resconv1(const float* __restrict__ w1,
                                                  const float4* __restrict__ sp,
                                                  float4* __restrict__ out) {
    if (blockIdx.x >= (unsigned)NB1) {
        copy_chunk(ST_RES + (int)blockIdx.x - NB1, sp, out);
        return;
    }
    __shared__ float dms[38][40];
    __shared__ float rs[18][20];
    __shared__ float sw[72];
    __shared__ float wred[16 * 8];
    int wid0 = blockIdx.x;
    int bx = wid0 % TW, by = (wid0 / TW) % TH, b = wid0 / (TW * TH);
    int x0 = bx * 16, y0 = by * 16;
    int tid = threadIdx.x;
    if (tid < 72) sw[tid] = w1[tid];
    const float* dm = d_dm + b * NYNX;
    int gy0 = 2 * y0 - 3, gx0 = 2 * x0 - 3;
    for (int i = tid; i < 38 * 38; i += 256) {
        int ly = i / 38, lx = i - ly * 38;
        int gy = gy0 + ly, gx = gx0 + lx;
        dms[ly][lx] = (gy >= 0 && gy < NYg && gx >= 0 && gx < NXg)
                          ? dm[gy * NXg + gx] : 0.f;
    }
    __syncthreads();
    float mx = __int_as_float(d_max[b]);
    float inv_mx = (mx > 0.f) ? (1.f / mx) : 1.f;
    for (int i = tid; i < 18 * 18; i += 256) {
        int ly = i / 18, lx = i - ly * 18;
        int yr = y0 - 1 + ly, xr = x0 - 1 + lx;
        float wy[4], wx[4]; int ry[4], rx[4];
        float sy = 0.f, sx = 0.f;
        #pragma unroll
        for (int j = 0; j < 4; j++) {
            float w = (j == 0 || j == 3) ? 0.25f : 0.75f;
            int r = 2 * yr - 1 + j;
            bool vr = (r >= 0) && (r < NYg);
            wy[j] = vr ? w : 0.f; ry[j] = vr ? (r - gy0) : 0; sy += wy[j];
            int c = 2 * xr - 1 + j;
            bool vc = (c >= 0) && (c < NXg);
            wx[j] = vc ? w : 0.f; rx[j] = vc ? (c - gx0) : 0; sx += wx[j];
        }
        #pragma unroll
        for (int j = 0; j < 4; j++) { wy[j] /= sy; wx[j] /= sx; }
        float acc = 0.f;
        #pragma unroll
        for (int jy = 0; jy < 4; jy++) {
            float r = 0.f;
            #pragma unroll
            for (int jx = 0; jx < 4; jx++) r = fmaf(wx[jx], dms[ry[jy]][rx[jx]], r);
            acc = fmaf(wy[jy], r, acc);
        }
        rs[ly][lx] = acc * inv_mx;
    }
    __syncthreads();
    int ty = tid >> 4, tx = tid & 15;
    int y = y0 + ty, x = x0 + tx;
    float acc[8] = {0.f,0.f,0.f,0.f,0.f,0.f,0.f,0.f};
    if (y < Hh && x < Ww) {
        #pragma unroll
        for (int ky = 0; ky < 3; ky++) {
            int yy = y + ky - 1;
            if (yy < 0 || yy >= Hh) continue;
            #pragma unroll
            for (int kx = 0; kx < 3; kx++) {
                int xx = x + kx - 1;
                if (xx < 0 || xx >= Ww) continue;
                float vv = rs[ty + ky][tx + kx];
                int wi = ky * 3 + kx;
                #pragma unroll
                for (int c = 0; c < 8; c++) acc[c] = fmaf(vv, sw[c * 9 + wi], acc[c]);
            }
        }
        float* dst = d_buf1 + (size_t)(b * 8) * HW + y * Ww + x;
        #pragma unroll
        for (int c = 0; c < 8; c++) dst[c * HW] = acc[c];
    }
    int lane = tid & 31, warp = tid >> 5;
    #pragma unroll
    for (int q = 0; q < 16; q++) {
        int c = q >> 1;
        float vv = (q & 1) ? acc[c] * acc[c] : acc[c];
        #pragma unroll
        for (int s = 16; s > 0; s >>= 1) vv += __shfl_down_sync(0xffffffffu, vv, s);
        if (lane == 0) wred[q * 8 + warp] = vv;
    }
    __syncthreads();
    if (tid < 16) {
        float s = 0.f;
        #pragma unroll
        for (int w = 0; w < 8; w++) s += wred[tid * 8 + w];
        d_part1[tid * NB1 + wid0] = s;
    }
}

__global__ void k_stats1(const float* __restrict__ g, const float* __restrict__ be,
                         const float4* __restrict__ sp, float4* __restrict__ out) {
    if (blockIdx.x >= 1) {
        copy_chunk(ST_S1 + (int)blockIdx.x - 1, sp, out);
        return;
    }
    __shared__ float sums[16];
    int tid = threadIdx.x;
    if (tid < 128) {
        int q = tid >> 3, l = tid & 7;
        float s = 0.f;
        #pragma unroll 4
        for (int i = l; i < NB1; i += 8) s += d_part1[q * NB1 + i];
        #pragma unroll
        for (int o = 4; o > 0; o >>= 1) s += __shfl_down_sync(0xffffffffu, s, o, 8);
        if (l == 0) sums[q] = s;
    }
    __syncthreads();
    if (tid < 8) {
        float mean = sums[tid * 2] / (float)CNT;
        float var  = sums[tid * 2 + 1] / (float)CNT - mean * mean;
        float inv  = rsqrtf(var + BN_EPS);
        float sc   = g[tid] * inv;
        d_sc1[tid] = sc;
        d_sh1[tid] = be[tid] - mean * sc;
    }
}

// bn1+relu on load, tiled conv3x3 8->16 in smem, BN2 partial stats
__global__ __launch_bounds__(256) void k_conv2(const float* __restrict__ w2,
                                               const float4* __restrict__ sp,
                                               float4* __restrict__ out) {
    if (blockIdx.x >= (unsigned)NB1) {
        copy_chunk(ST_CONV2 + (int)blockIdx.x - NB1, sp, out);
        return;
    }
    __shared__ float hs[8][18][20];
    __shared__ float sw[1152];
    __shared__ float ssc[8], ssh[8];
    __shared__ float wred[32 * 8];
    int wid0 = blockIdx.x;
    int bx = wid0 % TW, by = (wid0 / TW) % TH, b = wid0 / (TW * TH);
    int x0 = bx * 16, y0 = by * 16;
    int tid = threadIdx.x;
    for (int i = tid; i < 1152; i += 256) sw[i] = w2[i];
    if (tid < 8) { ssc[tid] = d_sc1[tid]; ssh[tid] = d_sh1[tid]; }
    __syncthreads();
    const float* src = d_buf1 + (size_t)(b * 8) * HW;
    for (int i = tid; i < 8 * 18 * 18; i += 256) {
        int c = i / 324; int r = i - c * 324;
        int ly = r / 18, lx = r - ly * 18;
        int gy = y0 - 1 + ly, gx = x0 - 1 + lx;
        float v = 0.f;
        if (gy >= 0 && gy < Hh && gx >= 0 && gx < Ww) {
            v = fmaxf(fmaf(src[c * HW + gy * Ww + gx], ssc[c], ssh[c]), 0.f);
        }
        hs[c][ly][lx] = v;
    }
    __syncthreads();
    int ty = tid >> 4, tx = tid & 15;
    int y = y0 + ty, x = x0 + tx;
    float acc[16];
    #pragma unroll
    for (int i = 0; i < 16; i++) acc[i] = 0.f;
    if (y < Hh && x < Ww) {
        #pragma unroll
        for (int ky = 0; ky < 3; ky++) {
            #pragma unroll
            for (int kx = 0; kx < 3; kx++) {
                int wi = ky * 3 + kx;
                #pragma unroll
                for (int ic = 0; ic < 8; ic++) {
                    float hv = hs[ic][ty + ky][tx + kx];
                    #pragma unroll
                    for (int oc = 0; oc < 16; oc++)
                        acc[oc] = fmaf(hv, sw[(oc * 8 + ic) * 9 + wi], acc[oc]);
                }
            }
        }
        float* dst = d_buf2 + (size_t)(b * 16) * HW + y * Ww + x;
        #pragma unroll
        for (int oc = 0; oc < 16; oc++) dst[oc * HW] = acc[oc];
    }
    int lane = tid & 31, warp = tid >> 5;
    #pragma unroll
    for (int q = 0; q < 32; q++) {
        int c = q >> 1;
        float v = (q & 1) ? acc[c] * acc[c] : acc[c];
        #pragma unroll
        for (int s = 16; s > 0; s >>= 1) v += __shfl_down_sync(0xffffffffu, v, s);
        if (lane == 0) wred[q * 8 + warp] = v;
    }
    __syncthreads();
    if (tid < 32) {
        float s = 0.f;
        #pragma unroll
        for (int w = 0; w < 8; w++) s += wred[tid * 8 + w];
        d_part2[tid * NB1 + wid0] = s;
    }
}

__global__ void k_stats2(const float* __restrict__ g, const float* __restrict__ be,
                         const float4* __restrict__ sp, float4* __restrict__ out) {
    if (blockIdx.x >= 1) {
        copy_chunk(ST_S2 + (int)blockIdx.x - 1, sp, out);
        return;
    }
    __shared__ float sums[32];
    int tid = threadIdx.x;
    int q = tid >> 3, l = tid & 7;
    float s = 0.f;
    #pragma unroll 4
    for (int i = l; i < NB1; i += 8) s += d_part2[q * NB1 + i];
    #pragma unroll
    for (int o = 4; o > 0; o >>= 1) s += __shfl_down_sync(0xffffffffu, s, o, 8);
    if (l == 0) sums[q] = s;
    __syncthreads();
    if (tid < 16) {
        float mean = sums[tid * 2] / (float)CNT;
        float var  = sums[tid * 2 + 1] / (float)CNT - mean * mean;
        float inv  = rsqrtf(var + BN_EPS);
        float sc   = g[tid] * inv;
        d_sc2[tid] = sc;
        d_sh2[tid] = be[tid] - mean * sc;
    }
}

// density channels: bn2+relu written to out channels [384,400); flat, 1 f4/thread
__global__ __launch_bounds__(256) void k_dens(float4* __restrict__ out) {
    constexpr int N4 = Bb * NDF * PL4;    // 857088
    int i = blockIdx.x * 256 + threadIdx.x;
    if (i >= N4) return;
    int b = i / (NDF * PL4);
    int r = i - b * (NDF * PL4);
    int c = r / PL4;
    float4 v = reinterpret_cast<const float4*>(d_buf2)[i];
    float sc = d_sc2[c], sh = d_sh2[c];
    v.x = fmaxf(fmaf(v.x, sc, sh), 0.f);
    v.y = fmaxf(fmaf(v.y, sc, sh), 0.f);
    v.z = fmaxf(fmaf(v.z, sc, sh), 0.f);
    v.w = fmaxf(fmaf(v.w, sc, sh), 0.f);
    out[b * BP4 + C_IN * PL4 + (r - c * PL4) + c * PL4] = v;
}

// ---------------- launch ----------------
extern "C" void kernel_launch(void* const* d_in, const int* in_sizes, int n_in,
                              void* d_out, int out_size) {
    const float* spatial = (const float*)d_in[0];
    const float* points  = (const float*)d_in[1];
    const float* w1 = (const float*)d_in[2];
    const float* g1 = (const float*)d_in[3];
    const float* b1 = (const float*)d_in[4];
    const float* w2 = (const float*)d_in[5];
    const float* g2 = (const float*)d_in[6];
    const float* b2 = (const float*)d_in[7];
    const float4* sp4 = (const float4*)spatial;
    float4* out4 = (float4*)d_out;
    int npts = in_sizes[1] / 5;
    int nbH = (npts + 255) / 256;

    k_init<<<512 + CP_INIT, 256>>>(sp4, out4);
    k_hist<<<nbH + CP_HIST, 256>>>(points, npts, nbH, sp4, out4);
    k_blur<<<14 * 16 * Bb + CP_BLUR, 256>>>(sp4, out4);
    k_resconv1<<<NB1 + CP_RES, 256>>>(w1, sp4, out4);
    k_stats1<<<1 + CP_S1, 256>>>(g1, b1, sp4, out4);
    k_conv2<<<NB1 + CP_CONV2, 256>>>(w2, sp4, out4);
    k_stats2<<<1 + CP_S2, 256>>>(g2, b2, sp4, out4);
    k_dens<<<(Bb * NDF * PL4 + 255) / 256, 256>>>(out4);
}

// round 9
// speedup vs baseline: 2.4349x; 2.4349x over previous
#include <cuda_runtime.h>
#include <math.h>

// ---------------- static config ----------------
constexpr int NXg = 432, NYg = 496, Bb = 4;
constexpr int Hh = 248, Ww = 216;
constexpr int HW = Hh * Ww;            // 53568
constexpr int C_IN = 384, NDF = 16;
constexpr int NYNX = NYg * NXg;        // 214272
constexpr int KS = 15, RR = 7;
constexpr int NBX = (HW + 255) / 256;  // 210
constexpr int NB_TOT = NBX * Bb;       // 840
constexpr float BN_EPS = 1e-3f;
constexpr int CNT = Bb * HW;           // 214272
constexpr int PL4 = HW / 4;            // 13392
constexpr int SP4 = C_IN * PL4;        // spatial float4 per batch
constexpr int BP4 = (C_IN + NDF) * PL4;// out float4 per batch
constexpr int OUT4 = Bb * BP4;         // 21,427,200 total out float4

// ---------------- scratch (static, no allocation) ----------------
__device__ int   d_hist[Bb * NYNX];
__device__ float d_tmp [Bb * NYNX];
__device__ float d_dm  [Bb * NYNX];
__device__ int   d_max [Bb];
__device__ float d_gauss[KS];
__device__ float d_dmr [Bb * HW];
__device__ float d_buf1[Bb * 8  * HW];
__device__ float d_buf2[Bb * 16 * HW];
__device__ float d_part1[16 * NB_TOT];
__device__ float d_part2[32 * NB_TOT];
__device__ float d_sc1[8],  d_sh1[8];
__device__ float d_sc2[16], d_sh2[16];

// ---------------- kernels (identical to the 221us R1 version) ----------------
__global__ void k_init() {
    int i = blockIdx.x * blockDim.x + threadIdx.x;
    int stride = gridDim.x * blockDim.x;
    for (int p = i; p < Bb * NYNX; p += stride) d_hist[p] = 0;
    if (i < Bb) d_max[i] = 0;
    if (i == 0) {
        float g[KS]; float s = 0.f;
        #pragma unroll
        for (int k = 0; k < KS; k++) {
            float c = (float)(k - RR);
            g[k] = expf(-(c * c) / 78.125f);   // 2*sigma^2, sigma=6.25
            s += g[k];
        }
        #pragma unroll
        for (int k = 0; k < KS; k++) d_gauss[k] = g[k] / s;
    }
}

__global__ void k_hist(const float* __restrict__ pts, int n) {
    int i = blockIdx.x * blockDim.x + threadIdx.x;
    if (i >= n) return;
    float b_f = pts[i * 5 + 0];
    float px  = pts[i * 5 + 1];
    float py  = pts[i * 5 + 2];
    int b  = (int)b_f;
    int xi = (int)__fdiv_rn(px - 0.0f, 0.16f);      // match f32 division exactly
    int yi = (int)__fdiv_rn(py - (-39.68f), 0.16f);
    xi = min(max(xi, 0), NXg - 1);
    yi = min(max(yi, 0), NYg - 1);
    atomicAdd(&d_hist[b * NYNX + yi * NXg + xi], 1);
}

// vertical blur (zero padding), int hist -> float tmp
__global__ void k_vblur() {
    int p = blockIdx.x * 256 + threadIdx.x;
    int b = blockIdx.y;
    if (p >= NYNX) return;
    int y = p / NXg, x = p - y * NXg;
    const int* h = d_hist + b * NYNX;
    float acc = 0.f;
    #pragma unroll
    for (int j = 0; j < KS; j++) {
        int yy = y + j - RR;
        if (yy >= 0 && yy < NYg) acc = fmaf(d_gauss[j], (float)h[yy * NXg + x], acc);
    }
    d_tmp[b * NYNX + p] = acc;
}

// horizontal blur (zero padding) + per-batch max reduce
__global__ void k_hblur() {
    __shared__ float red[256];
    int tid = threadIdx.x;
    int p = blockIdx.x * 256 + tid;
    int b = blockIdx.y;
    float acc = 0.f;
    if (p < NYNX) {
        int y = p / NXg, x = p - y * NXg;
        const float* t = d_tmp + b * NYNX + y * NXg;
        #pragma unroll
        for (int j = 0; j < KS; j++) {
            int xx = x + j - RR;
            if (xx >= 0 && xx < NXg) acc = fmaf(d_gauss[j], t[xx], acc);
        }
        d_dm[b * NYNX + p] = acc;
    }
    red[tid] = acc;
    __syncthreads();
    for (int s = 128; s > 0; s >>= 1) {
        if (tid < s) red[tid] = fmaxf(red[tid], red[tid + s]);
        __syncthreads();
    }
    if (tid == 0) atomicMax(&d_max[b], __float_as_int(red[0]));  // values >= 0
}

// antialiased 2x downsample (jax.image.resize linear, antialias=True) + /max
__global__ void k_resize() {
    int p = blockIdx.x * 256 + threadIdx.x;
    int b = blockIdx.y;
    if (p >= HW) return;
    int y = p / Ww, x = p - y * Ww;

    float wy[4], wx[4]; int ry[4], rx[4];
    float sy = 0.f, sx = 0.f;
    #pragma unroll
    for (int j = 0; j < 4; j++) {
        float w = (j == 0 || j == 3) ? 0.25f : 0.75f;
        int r = 2 * y - 1 + j;
        bool v = (r >= 0) && (r < NYg);
        wy[j] = v ? w : 0.f; ry[j] = v ? r : 0; sy += wy[j];
        int c = 2 * x - 1 + j;
        bool vc = (c >= 0) && (c < NXg);
        wx[j] = vc ? w : 0.f; rx[j] = vc ? c : 0; sx += wx[j];
    }
    #pragma unroll
    for (int j = 0; j < 4; j++) { wy[j] /= sy; wx[j] /= sx; }

    const float* dm = d_dm + b * NYNX;
    float acc = 0.f;
    #pragma unroll
    for (int jy = 0; jy < 4; jy++) {
        const float* row = dm + ry[jy] * NXg;
        float r = 0.f;
        #pragma unroll
        for (int jx = 0; jx < 4; jx++) r = fmaf(wx[jx], row[rx[jx]], r);
        acc = fmaf(wy[jy], r, acc);
    }
    float mx = __int_as_float(d_max[b]);
    d_dmr[b * HW + p] = (mx > 0.f) ? __fdiv_rn(acc, mx) : acc;
}

// conv3x3 1->8 (zero pad) + per-block partial sums for BN1
__global__ void k_conv1(const float* __restrict__ w1) {
    __shared__ float sw[72];
    __shared__ float wred[16 * 8];
    int tid = threadIdx.x;
    if (tid < 72) sw[tid] = w1[tid];
    __syncthreads();

    int p = blockIdx.x * 256 + tid;
    int b = blockIdx.y;
    float acc[8] = {0.f,0.f,0.f,0.f,0.f,0.f,0.f,0.f};
    if (p < HW) {
        int y = p / Ww, x = p - y * Ww;
        const float* src = d_dmr + b * HW;
        #pragma unroll
        for (int ky = 0; ky < 3; ky++) {
            int yy = y + ky - 1;
            if (yy < 0 || yy >= Hh) continue;
            #pragma unroll
            for (int kx = 0; kx < 3; kx++) {
                int xx = x + kx - 1;
                if (xx < 0 || xx >= Ww) continue;
                float v = src[yy * Ww + xx];
                int wi = ky * 3 + kx;
                #pragma unroll
                for (int c = 0; c < 8; c++) acc[c] = fmaf(v, sw[c * 9 + wi], acc[c]);
            }
        }
        float* dst = d_buf1 + (size_t)(b * 8) * HW + p;
        #pragma unroll
        for (int c = 0; c < 8; c++) dst[c * HW] = acc[c];
    }
    // deterministic fixed-tree stats: 16 quantities (sum, sumsq per channel)
    int lane = tid & 31, wid = tid >> 5;
    int blk = blockIdx.y * gridDim.x + blockIdx.x;
    #pragma unroll
    for (int q = 0; q < 16; q++) {
        int c = q >> 1;
        float v = (q & 1) ? acc[c] * acc[c] : acc[c];
        #pragma unroll
        for (int s = 16; s > 0; s >>= 1) v += __shfl_down_sync(0xffffffffu, v, s);
        if (lane == 0) wred[q * 8 + wid] = v;
    }
    __syncthreads();
    if (tid < 16) {
        float s = 0.f;
        #pragma unroll
        for (int w = 0; w < 8; w++) s += wred[tid * 8 + w];
        d_part1[tid * NB_TOT + blk] = s;
    }
}

__global__ void k_stats1(const float* __restrict__ g, const float* __restrict__ be) {
    int tid = threadIdx.x;
    __shared__ float sums[16];
    if (tid < 16) {
        float s = 0.f;
        for (int i = 0; i < NB_TOT; i++) s += d_part1[tid * NB_TOT + i];
        sums[tid] = s;
    }
    __syncthreads();
    if (tid < 8) {
        float mean = sums[tid * 2] / (float)CNT;
        float var  = sums[tid * 2 + 1] / (float)CNT - mean * mean;
        float inv  = rsqrtf(var + BN_EPS);
        float sc   = g[tid] * inv;
        d_sc1[tid] = sc;
        d_sh1[tid] = be[tid] - mean * sc;
    }
}

// bn1+relu applied on the fly, conv3x3 8->16 (zero pad on h), partial stats for BN2
__global__ void k_conv2(const float* __restrict__ w2) {
    __shared__ float sw[1152];
    __shared__ float ssc[8], ssh[8];
    __shared__ float wred[32 * 8];
    int tid = threadIdx.x;
    for (int i = tid; i < 1152; i += 256) sw[i] = w2[i];
    if (tid < 8) { ssc[tid] = d_sc1[tid]; ssh[tid] = d_sh1[tid]; }
    __syncthreads();

    int p = blockIdx.x * 256 + tid;
    int b = blockIdx.y;
    float acc[16];
    #pragma unroll
    for (int i = 0; i < 16; i++) acc[i] = 0.f;
    if (p < HW) {
        int y = p / Ww, x = p - y * Ww;
        const float* src = d_buf1 + (size_t)(b * 8) * HW;
        #pragma unroll
        for (int ky = 0; ky < 3; ky++) {
            int yy = y + ky - 1;
            if (yy < 0 || yy >= Hh) continue;
            #pragma unroll
            for (int kx = 0; kx < 3; kx++) {
                int xx = x + kx - 1;
                if (xx < 0 || xx >= Ww) continue;
                int off = yy * Ww + xx;
                int wi = ky * 3 + kx;
                float hbuf[8];
                #pragma unroll
                for (int c = 0; c < 8; c++) {
                    float v = src[c * HW + off];
                    hbuf[c] = fmaxf(fmaf(v, ssc[c], ssh[c]), 0.f);
                }
                #pragma unroll
                for (int oc = 0; oc < 16; oc++) {
                    #pragma unroll
                    for (int ic = 0; ic < 8; ic++)
                        acc[oc] = fmaf(hbuf[ic], sw[(oc * 8 + ic) * 9 + wi], acc[oc]);
                }
            }
        }
        float* dst = d_buf2 + (size_t)(b * 16) * HW + p;
        #pragma unroll
        for (int oc = 0; oc < 16; oc++) dst[oc * HW] = acc[oc];
    }
    int lane = tid & 31, wid = tid >> 5;
    int blk = blockIdx.y * gridDim.x + blockIdx.x;
    #pragma unroll
    for (int q = 0; q < 32; q++) {
        int c = q >> 1;
        float v = (q & 1) ? acc[c] * acc[c] : acc[c];
        #pragma unroll
        for (int s = 16; s > 0; s >>= 1) v += __shfl_down_sync(0xffffffffu, v, s);
        if (lane == 0) wred[q * 8 + wid] = v;
    }
    __syncthreads();
    if (tid < 32) {
        float s = 0.f;
        #pragma unroll
        for (int w = 0; w < 8; w++) s += wred[tid * 8 + w];
        d_part2[tid * NB_TOT + blk] = s;
    }
}

__global__ void k_stats2(const float* __restrict__ g, const float* __restrict__ be) {
    int tid = threadIdx.x;
    __shared__ float sums[32];
    if (tid < 32) {
        float s = 0.f;
        for (int i = 0; i < NB_TOT; i++) s += d_part2[tid * NB_TOT + i];
        sums[tid] = s;
    }
    __syncthreads();
    if (tid < 16) {
        float mean = sums[tid * 2] / (float)CNT;
        float var  = sums[tid * 2 + 1] / (float)CNT - mean * mean;
        float inv  = rsqrtf(var + BN_EPS);
        float sc   = g[tid] * inv;
        d_sc2[tid] = sc;
        d_sh2[tid] = be[tid] - mean * sc;
    }
}

// ---- single flat output writer, 4 independent float4 per thread (MLP=4) ----
// Covers all OUT4 float4: spatial passthrough for channels [0,384),
// bn2+relu density for [384,400).
__global__ __launch_bounds__(256) void k_out(const float4* __restrict__ sp,
                                             float4* __restrict__ out) {
    int base = blockIdx.x * 1024 + (int)threadIdx.x;

    int j[4];
    const float4* p[4];
    bool dens[4];
    int rr[4];
    #pragma unroll
    for (int u = 0; u < 4; u++) {
        j[u] = base + u * 256;
        int b = j[u] / BP4;
        int r = j[u] - b * BP4;
        dens[u] = (r >= SP4);
        rr[u] = r - SP4;
        p[u] = dens[u]
            ? reinterpret_cast<const float4*>(d_buf2) + (b * NDF * PL4 + rr[u])
            : sp + (b * SP4 + r);
    }
    float4 v[4];
    v[0] = *p[0];
    v[1] = *p[1];
    v[2] = *p[2];
    v[3] = *p[3];
    #pragma unroll
    for (int u = 0; u < 4; u++) {
        if (dens[u]) {
            int c = rr[u] / PL4;
            float sc = d_sc2[c], sh = d_sh2[c];
            v[u].x = fmaxf(fmaf(v[u].x, sc, sh), 0.f);
            v[u].y = fmaxf(fmaf(v[u].y, sc, sh), 0.f);
            v[u].z = fmaxf(fmaf(v[u].z, sc, sh), 0.f);
            v[u].w = fmaxf(fmaf(v[u].w, sc, sh), 0.f);
        }
    }
    #pragma unroll
    for (int u = 0; u < 4; u++) out[j[u]] = v[u];
}

// ---------------- launch ----------------
extern "C" void kernel_launch(void* const* d_in, const int* in_sizes, int n_in,
                              void* d_out, int out_size) {
    const float* spatial = (const float*)d_in[0];
    const float* points  = (const float*)d_in[1];
    const float* w1 = (const float*)d_in[2];
    const float* g1 = (const float*)d_in[3];
    const float* b1 = (const float*)d_in[4];
    const float* w2 = (const float*)d_in[5];
    const float* g2 = (const float*)d_in[6];
    const float* b2 = (const float*)d_in[7];
    float* out = (float*)d_out;
    int npts = in_sizes[1] / 5;

    k_init<<<512, 256>>>();
    k_hist<<<(npts + 255) / 256, 256>>>(points, npts);
    dim3 gb((NYNX + 255) / 256, Bb);
    k_vblur<<<gb, 256>>>();
    k_hblur<<<gb, 256>>>();
    dim3 gh(NBX, Bb);
    k_resize<<<gh, 256>>>();
    k_conv1<<<gh, 256>>>(w1);
    k_stats1<<<1, 64>>>(g1, b1);
    k_conv2<<<gh, 256>>>(w2);
    k_stats2<<<1, 64>>>(g2, b2);
    static_assert(OUT4 % 1024 == 0, "grid");
    k_out<<<OUT4 / 1024, 256>>>((const float4*)spatial, (float4*)out);
}

// round 11
// speedup vs baseline: 2.4629x; 1.0115x over previous
#include <cuda_runtime.h>
#include <math.h>

// ---------------- static config ----------------
constexpr int NXg = 432, NYg = 496, Bb = 4;
constexpr int Hh = 248, Ww = 216;
constexpr int HW = Hh * Ww;            // 53568
constexpr int C_IN = 384, NDF = 16;
constexpr int NYNX = NYg * NXg;        // 214272
constexpr int KS = 15, RR = 7;
constexpr int NBX = (HW + 255) / 256;  // 210
constexpr int NB_TOT = NBX * Bb;       // 840
constexpr float BN_EPS = 1e-3f;
constexpr int CNT = Bb * HW;           // 214272
constexpr int PL4 = HW / 4;            // 13392
constexpr int SP4 = C_IN * PL4;        // spatial float4 per batch
constexpr int BP4 = (C_IN + NDF) * PL4;// out float4 per batch
constexpr int NCP = Bb * SP4;          // 20,570,112 copy float4 total

// ---------------- scratch (static, no allocation) ----------------
__device__ int   d_hist[Bb * NYNX];
__device__ float d_tmp [Bb * NYNX];
__device__ float d_dm  [Bb * NYNX];
__device__ int   d_max [Bb];
__device__ float d_gauss[KS];
__device__ float d_dmr [Bb * HW];
__device__ float d_buf1[Bb * 8  * HW];
__device__ float d_buf2[Bb * 16 * HW];
__device__ float d_part1[16 * NB_TOT];
__device__ float d_part2[32 * NB_TOT];
__device__ float d_sc1[8],  d_sh1[8];
__device__ float d_sc2[16], d_sh2[16];

// ---------------- kernels (pipeline identical to the 219us version) ----------
__global__ void k_init() {
    int i = blockIdx.x * blockDim.x + threadIdx.x;
    int stride = gridDim.x * blockDim.x;
    for (int p = i; p < Bb * NYNX; p += stride) d_hist[p] = 0;
    if (i < Bb) d_max[i] = 0;
    if (i == 0) {
        float g[KS]; float s = 0.f;
        #pragma unroll
        for (int k = 0; k < KS; k++) {
            float c = (float)(k - RR);
            g[k] = expf(-(c * c) / 78.125f);   // 2*sigma^2, sigma=6.25
            s += g[k];
        }
        #pragma unroll
        for (int k = 0; k < KS; k++) d_gauss[k] = g[k] / s;
    }
}

__global__ void k_hist(const float* __restrict__ pts, int n) {
    int i = blockIdx.x * blockDim.x + threadIdx.x;
    if (i >= n) return;
    float b_f = pts[i * 5 + 0];
    float px  = pts[i * 5 + 1];
    float py  = pts[i * 5 + 2];
    int b  = (int)b_f;
    int xi = (int)__fdiv_rn(px - 0.0f, 0.16f);      // match f32 division exactly
    int yi = (int)__fdiv_rn(py - (-39.68f), 0.16f);
    xi = min(max(xi, 0), NXg - 1);
    yi = min(max(yi, 0), NYg - 1);
    atomicAdd(&d_hist[b * NYNX + yi * NXg + xi], 1);
}

// vertical blur (zero padding), int hist -> float tmp
__global__ void k_vblur() {
    int p = blockIdx.x * 256 + threadIdx.x;
    int b = blockIdx.y;
    if (p >= NYNX) return;
    int y = p / NXg, x = p - y * NXg;
    const int* h = d_hist + b * NYNX;
    float acc = 0.f;
    #pragma unroll
    for (int j = 0; j < KS; j++) {
        int yy = y + j - RR;
        if (yy >= 0 && yy < NYg) acc = fmaf(d_gauss[j], (float)h[yy * NXg + x], acc);
    }
    d_tmp[b * NYNX + p] = acc;
}

// horizontal blur (zero padding) + per-batch max reduce
__global__ void k_hblur() {
    __shared__ float red[256];
    int tid = threadIdx.x;
    int p = blockIdx.x * 256 + tid;
    int b = blockIdx.y;
    float acc = 0.f;
    if (p < NYNX) {
        int y = p / NXg, x = p - y * NXg;
        const float* t = d_tmp + b * NYNX + y * NXg;
        #pragma unroll
        for (int j = 0; j < KS; j++) {
            int xx = x + j - RR;
            if (xx >= 0 && xx < NXg) acc = fmaf(d_gauss[j], t[xx], acc);
        }
        d_dm[b * NYNX + p] = acc;
    }
    red[tid] = acc;
    __syncthreads();
    for (int s = 128; s > 0; s >>= 1) {
        if (tid < s) red[tid] = fmaxf(red[tid], red[tid + s]);
        __syncthreads();
    }
    if (tid == 0) atomicMax(&d_max[b], __float_as_int(red[0]));  // values >= 0
}

// antialiased 2x downsample (jax.image.resize linear, antialias=True) + /max
__global__ void k_resize() {
    int p = blockIdx.x * 256 + threadIdx.x;
    int b = blockIdx.y;
    if (p >= HW) return;
    int y = p / Ww, x = p - y * Ww;

    float wy[4], wx[4]; int ry[4], rx[4];
    float sy = 0.f, sx = 0.f;
    #pragma unroll
    for (int j = 0; j < 4; j++) {
        float w = (j == 0 || j == 3) ? 0.25f : 0.75f;
        int r = 2 * y - 1 + j;
        bool v = (r >= 0) && (r < NYg);
        wy[j] = v ? w : 0.f; ry[j] = v ? r : 0; sy += wy[j];
        int c = 2 * x - 1 + j;
        bool vc = (c >= 0) && (c < NXg);
        wx[j] = vc ? w : 0.f; rx[j] = vc ? c : 0; sx += wx[j];
    }
    #pragma unroll
    for (int j = 0; j < 4; j++) { wy[j] /= sy; wx[j] /= sx; }

    const float* dm = d_dm + b * NYNX;
    float acc = 0.f;
    #pragma unroll
    for (int jy = 0; jy < 4; jy++) {
        const float* row = dm + ry[jy] * NXg;
        float r = 0.f;
        #pragma unroll
        for (int jx = 0; jx < 4; jx++) r = fmaf(wx[jx], row[rx[jx]], r);
        acc = fmaf(wy[jy], r, acc);
    }
    float mx = __int_as_float(d_max[b]);
    d_dmr[b * HW + p] = (mx > 0.f) ? __fdiv_rn(acc, mx) : acc;
}

// conv3x3 1->8 (zero pad) + per-block partial sums for BN1
__global__ void k_conv1(const float* __restrict__ w1) {
    __shared__ float sw[72];
    __shared__ float wred[16 * 8];
    int tid = threadIdx.x;
    if (tid < 72) sw[tid] = w1[tid];
    __syncthreads();

    int p = blockIdx.x * 256 + tid;
    int b = blockIdx.y;
    float acc[8] = {0.f,0.f,0.f,0.f,0.f,0.f,0.f,0.f};
    if (p < HW) {
        int y = p / Ww, x = p - y * Ww;
        const float* src = d_dmr + b * HW;
        #pragma unroll
        for (int ky = 0; ky < 3; ky++) {
            int yy = y + ky - 1;
            if (yy < 0 || yy >= Hh) continue;
            #pragma unroll
            for (int kx = 0; kx < 3; kx++) {
                int xx = x + kx - 1;
                if (xx < 0 || xx >= Ww) continue;
                float v = src[yy * Ww + xx];
                int wi = ky * 3 + kx;
                #pragma unroll
                for (int c = 0; c < 8; c++) acc[c] = fmaf(v, sw[c * 9 + wi], acc[c]);
            }
        }
        float* dst = d_buf1 + (size_t)(b * 8) * HW + p;
        #pragma unroll
        for (int c = 0; c < 8; c++) dst[c * HW] = acc[c];
    }
    // deterministic fixed-tree stats: 16 quantities (sum, sumsq per channel)
    int lane = tid & 31, wid = tid >> 5;
    int blk = blockIdx.y * gridDim.x + blockIdx.x;
    #pragma unroll
    for (int q = 0; q < 16; q++) {
        int c = q >> 1;
        float v = (q & 1) ? acc[c] * acc[c] : acc[c];
        #pragma unroll
        for (int s = 16; s > 0; s >>= 1) v += __shfl_down_sync(0xffffffffu, v, s);
        if (lane == 0) wred[q * 8 + wid] = v;
    }
    __syncthreads();
    if (tid < 16) {
        float s = 0.f;
        #pragma unroll
        for (int w = 0; w < 8; w++) s += wred[tid * 8 + w];
        d_part1[tid * NB_TOT + blk] = s;
    }
}

__global__ void k_stats1(const float* __restrict__ g, const float* __restrict__ be) {
    int tid = threadIdx.x;
    __shared__ float sums[16];
    if (tid < 16) {
        float s = 0.f;
        for (int i = 0; i < NB_TOT; i++) s += d_part1[tid * NB_TOT + i];
        sums[tid] = s;
    }
    __syncthreads();
    if (tid < 8) {
        float mean = sums[tid * 2] / (float)CNT;
        float var  = sums[tid * 2 + 1] / (float)CNT - mean * mean;
        float inv  = rsqrtf(var + BN_EPS);
        float sc   = g[tid] * inv;
        d_sc1[tid] = sc;
        d_sh1[tid] = be[tid] - mean * sc;
    }
}

// bn1+relu applied on the fly, conv3x3 8->16 (zero pad on h), partial stats for BN2
__global__ void k_conv2(const float* __restrict__ w2) {
    __shared__ float sw[1152];
    __shared__ float ssc[8], ssh[8];
    __shared__ float wred[32 * 8];
    int tid = threadIdx.x;
    for (int i = tid; i < 1152; i += 256) sw[i] = w2[i];
    if (tid < 8) { ssc[tid] = d_sc1[tid]; ssh[tid] = d_sh1[tid]; }
    __syncthreads();

    int p = blockIdx.x * 256 + tid;
    int b = blockIdx.y;
    float acc[16];
    #pragma unroll
    for (int i = 0; i < 16; i++) acc[i] = 0.f;
    if (p < HW) {
        int y = p / Ww, x = p - y * Ww;
        const float* src = d_buf1 + (size_t)(b * 8) * HW;
        #pragma unroll
        for (int ky = 0; ky < 3; ky++) {
            int yy = y + ky - 1;
            if (yy < 0 || yy >= Hh) continue;
            #pragma unroll
            for (int kx = 0; kx < 3; kx++) {
                int xx = x + kx - 1;
                if (xx < 0 || xx >= Ww) continue;
                int off = yy * Ww + xx;
                int wi = ky * 3 + kx;
                float hbuf[8];
                #pragma unroll
                for (int c = 0; c < 8; c++) {
                    float v = src[c * HW + off];
                    hbuf[c] = fmaxf(fmaf(v, ssc[c], ssh[c]), 0.f);
                }
                #pragma unroll
                for (int oc = 0; oc < 16; oc++) {
                    #pragma unroll
                    for (int ic = 0; ic < 8; ic++)
                        acc[oc] = fmaf(hbuf[ic], sw[(oc * 8 + ic) * 9 + wi], acc[oc]);
                }
            }
        }
        float* dst = d_buf2 + (size_t)(b * 16) * HW + p;
        #pragma unroll
        for (int oc = 0; oc < 16; oc++) dst[oc * HW] = acc[oc];
    }
    int lane = tid & 31, wid = tid >> 5;
    int blk = blockIdx.y * gridDim.x + blockIdx.x;
    #pragma unroll
    for (int q = 0; q < 32; q++) {
        int c = q >> 1;
        float v = (q & 1) ? acc[c] * acc[c] : acc[c];
        #pragma unroll
        for (int s = 16; s > 0; s >>= 1) v += __shfl_down_sync(0xffffffffu, v, s);
        if (lane == 0) wred[q * 8 + wid] = v;
    }
    __syncthreads();
    if (tid < 32) {
        float s = 0.f;
        #pragma unroll
        for (int w = 0; w < 8; w++) s += wred[tid * 8 + w];
        d_part2[tid * NB_TOT + blk] = s;
    }
}

__global__ void k_stats2(const float* __restrict__ g, const float* __restrict__ be) {
    int tid = threadIdx.x;
    __shared__ float sums[32];
    if (tid < 32) {
        float s = 0.f;
        for (int i = 0; i < NB_TOT; i++) s += d_part2[tid * NB_TOT + i];
        sums[tid] = s;
    }
    __syncthreads();
    if (tid < 16) {
        float mean = sums[tid * 2] / (float)CNT;
        float var  = sums[tid * 2 + 1] / (float)CNT - mean * mean;
        float inv  = rsqrtf(var + BN_EPS);
        float sc   = g[tid] * inv;
        d_sc2[tid] = sc;
        d_sh2[tid] = be[tid] - mean * sc;
    }
}

// density channels: bn2+relu into out channels [384,400) — default-stream branch
__global__ __launch_bounds__(256) void k_dens(float4* __restrict__ out) {
    constexpr int N4 = Bb * NDF * PL4;    // 857088
    int i = blockIdx.x * 256 + threadIdx.x;
    if (i >= N4) return;
    int b = i / (NDF * PL4);
    int r = i - b * (NDF * PL4);
    int c = r / PL4;
    float4 v = reinterpret_cast<const float4*>(d_buf2)[i];
    float sc = d_sc2[c], sh = d_sh2[c];
    v.x = fmaxf(fmaf(v.x, sc, sh), 0.f);
    v.y = fmaxf(fmaf(v.y, sc, sh), 0.f);
    v.z = fmaxf(fmaf(v.z, sc, sh), 0.f);
    v.w = fmaxf(fmaf(v.w, sc, sh), 0.f);
    out[(size_t)b * BP4 + SP4 + r] = v;
}

// spatial passthrough into out channels [0,384) — side-stream branch, MLP=4
__global__ __launch_bounds__(256) void k_copy(const float4* __restrict__ sp,
                                              float4* __restrict__ out) {
    int base = blockIdx.x * 1024 + (int)threadIdx.x;
    int j0 = base, j1 = base + 256, j2 = base + 512, j3 = base + 768;
    float4 v0 = sp[j0];
    float4 v1 = sp[j1];
    float4 v2 = sp[j2];
    float4 v3 = sp[j3];
    int b0 = j0 / SP4, b1 = j1 / SP4, b2 = j2 / SP4, b3 = j3 / SP4;
    out[b0 * BP4 + (j0 - b0 * SP4)] = v0;
    out[b1 * BP4 + (j1 - b1 * SP4)] = v1;
    out[b2 * BP4 + (j2 - b2 * SP4)] = v2;
    out[b3 * BP4 + (j3 - b3 * SP4)] = v3;
}

// ---------------- launch: forked-capture overlap ----------------
extern "C" void kernel_launch(void* const* d_in, const int* in_sizes, int n_in,
                              void* d_out, int out_size) {
    const float* spatial = (const float*)d_in[0];
    const float* points  = (const float*)d_in[1];
    const float* w1 = (const float*)d_in[2];
    const float* g1 = (const float*)d_in[3];
    const float* b1 = (const float*)d_in[4];
    const float* w2 = (const float*)d_in[5];
    const float* g2 = (const float*)d_in[6];
    const float* b2 = (const float*)d_in[7];
    float* out = (float*)d_out;
    const float4* sp4 = (const float4*)spatial;
    float4* out4 = (float4*)out;
    int npts = in_sizes[1] / 5;

    // side stream + events, created once on the first (non-capturing) call;
    // the same launch sequence is issued on every call (work is deterministic)
    static cudaStream_t s2 = nullptr;
    static cudaEvent_t eFork = nullptr, eJoin = nullptr;
    if (s2 == nullptr) {
        cudaStreamCreateWithFlags(&s2, cudaStreamNonBlocking);
        cudaEventCreateWithFlags(&eFork, cudaEventDisableTiming);
        cudaEventCreateWithFlags(&eJoin, cudaEventDisableTiming);
    }

    // fork: spatial passthrough copy runs concurrently with the density pipeline
    cudaEventRecord(eFork, 0);
    cudaStreamWaitEvent(s2, eFork, 0);
    static_assert(NCP % 1024 == 0, "copy grid");
    k_copy<<<NCP / 1024, 256, 0, s2>>>(sp4, out4);
    cudaEventRecord(eJoin, s2);

    // density pipeline on the default (capture) stream
    k_init<<<512, 256>>>();
    k_hist<<<(npts + 255) / 256, 256>>>(points, npts);
    dim3 gb((NYNX + 255) / 256, Bb);
    k_vblur<<<gb, 256>>>();
    k_hblur<<<gb, 256>>>();
    dim3 gh(NBX, Bb);
    k_resize<<<gh, 256>>>();
    k_conv1<<<gh, 256>>>(w1);
    k_stats1<<<1, 64>>>(g1, b1);
    k_conv2<<<gh, 256>>>(w2);
    k_stats2<<<1, 64>>>(g2, b2);
    k_dens<<<(Bb * NDF * PL4 + 255) / 256, 256>>>(out4);

    // join both branches before capture ends
    cudaStreamWaitEvent(0, eJoin, 0);
}

// round 12
// speedup vs baseline: 2.4834x; 1.0083x over previous
#include <cuda_runtime.h>
#include <math.h>

// ---------------- static config ----------------
constexpr int NXg = 432, NYg = 496, Bb = 4;
constexpr int Hh = 248, Ww = 216;
constexpr int HW = Hh * Ww;            // 53568
constexpr int C_IN = 384, NDF = 16;
constexpr int NYNX = NYg * NXg;        // 214272
constexpr int KS = 15, RR = 7;
constexpr int NBX = (HW + 255) / 256;  // 210
constexpr int NB_TOT = NBX * Bb;       // 840
constexpr float BN_EPS = 1e-3f;
constexpr int CNT = Bb * HW;           // 214272
constexpr int PL4 = HW / 4;            // 13392
constexpr int SP4 = C_IN * PL4;        // spatial float4 per batch
constexpr int BP4 = (C_IN + NDF) * PL4;// out float4 per batch
constexpr int NCP = Bb * SP4;          // 20,570,112 copy float4 total

// ---------------- scratch (static, no allocation) ----------------
__device__ int   d_hist[Bb * NYNX];
__device__ float d_tmp [Bb * NYNX];
__device__ float d_dm  [Bb * NYNX];
__device__ int   d_max [Bb];
__device__ float d_gauss[KS];
__device__ float d_dmr [Bb * HW];
__device__ float d_buf1[Bb * 8  * HW];
__device__ float d_buf2[Bb * 16 * HW];
__device__ float d_part1[16 * NB_TOT];
__device__ float d_part2[32 * NB_TOT];
__device__ float d_sc1[8],  d_sh1[8];
__device__ float d_sc2[16], d_sh2[16];

// ---------------- kernels (identical to the 217us version) ----------
__global__ void k_init() {
    int i = blockIdx.x * blockDim.x + threadIdx.x;
    int stride = gridDim.x * blockDim.x;
    for (int p = i; p < Bb * NYNX; p += stride) d_hist[p] = 0;
    if (i < Bb) d_max[i] = 0;
    if (i == 0) {
        float g[KS]; float s = 0.f;
        #pragma unroll
        for (int k = 0; k < KS; k++) {
            float c = (float)(k - RR);
            g[k] = expf(-(c * c) / 78.125f);   // 2*sigma^2, sigma=6.25
            s += g[k];
        }
        #pragma unroll
        for (int k = 0; k < KS; k++) d_gauss[k] = g[k] / s;
    }
}

__global__ void k_hist(const float* __restrict__ pts, int n) {
    int i = blockIdx.x * blockDim.x + threadIdx.x;
    if (i >= n) return;
    float b_f = pts[i * 5 + 0];
    float px  = pts[i * 5 + 1];
    float py  = pts[i * 5 + 2];
    int b  = (int)b_f;
    int xi = (int)__fdiv_rn(px - 0.0f, 0.16f);      // match f32 division exactly
    int yi = (int)__fdiv_rn(py - (-39.68f), 0.16f);
    xi = min(max(xi, 0), NXg - 1);
    yi = min(max(yi, 0), NYg - 1);
    atomicAdd(&d_hist[b * NYNX + yi * NXg + xi], 1);
}

// vertical blur (zero padding), int hist -> float tmp
__global__ void k_vblur() {
    int p = blockIdx.x * 256 + threadIdx.x;
    int b = blockIdx.y;
    if (p >= NYNX) return;
    int y = p / NXg, x = p - y * NXg;
    const int* h = d_hist + b * NYNX;
    float acc = 0.f;
    #pragma unroll
    for (int j = 0; j < KS; j++) {
        int yy = y + j - RR;
        if (yy >= 0 && yy < NYg) acc = fmaf(d_gauss[j], (float)h[yy * NXg + x], acc);
    }
    d_tmp[b * NYNX + p] = acc;
}

// horizontal blur (zero padding) + per-batch max reduce
__global__ void k_hblur() {
    __shared__ float red[256];
    int tid = threadIdx.x;
    int p = blockIdx.x * 256 + tid;
    int b = blockIdx.y;
    float acc = 0.f;
    if (p < NYNX) {
        int y = p / NXg, x = p - y * NXg;
        const float* t = d_tmp + b * NYNX + y * NXg;
        #pragma unroll
        for (int j = 0; j < KS; j++) {
            int xx = x + j - RR;
            if (xx >= 0 && xx < NXg) acc = fmaf(d_gauss[j], t[xx], acc);
        }
        d_dm[b * NYNX + p] = acc;
    }
    red[tid] = acc;
    __syncthreads();
    for (int s = 128; s > 0; s >>= 1) {
        if (tid < s) red[tid] = fmaxf(red[tid], red[tid + s]);
        __syncthreads();
    }
    if (tid == 0) atomicMax(&d_max[b], __float_as_int(red[0]));  // values >= 0
}

// antialiased 2x downsample (jax.image.resize linear, antialias=True) + /max
__global__ void k_resize() {
    int p = blockIdx.x * 256 + threadIdx.x;
    int b = blockIdx.y;
    if (p >= HW) return;
    int y = p / Ww, x = p - y * Ww;

    float wy[4], wx[4]; int ry[4], rx[4];
    float sy = 0.f, sx = 0.f;
    #pragma unroll
    for (int j = 0; j < 4; j++) {
        float w = (j == 0 || j == 3) ? 0.25f : 0.75f;
        int r = 2 * y - 1 + j;
        bool v = (r >= 0) && (r < NYg);
        wy[j] = v ? w : 0.f; ry[j] = v ? r : 0; sy += wy[j];
        int c = 2 * x - 1 + j;
        bool vc = (c >= 0) && (c < NXg);
        wx[j] = vc ? w : 0.f; rx[j] = vc ? c : 0; sx += wx[j];
    }
    #pragma unroll
    for (int j = 0; j < 4; j++) { wy[j] /= sy; wx[j] /= sx; }

    const float* dm = d_dm + b * NYNX;
    float acc = 0.f;
    #pragma unroll
    for (int jy = 0; jy < 4; jy++) {
        const float* row = dm + ry[jy] * NXg;
        float r = 0.f;
        #pragma unroll
        for (int jx = 0; jx < 4; jx++) r = fmaf(wx[jx], row[rx[jx]], r);
        acc = fmaf(wy[jy], r, acc);
    }
    float mx = __int_as_float(d_max[b]);
    d_dmr[b * HW + p] = (mx > 0.f) ? __fdiv_rn(acc, mx) : acc;
}

// conv3x3 1->8 (zero pad) + per-block partial sums for BN1
__global__ void k_conv1(const float* __restrict__ w1) {
    __shared__ float sw[72];
    __shared__ float wred[16 * 8];
    int tid = threadIdx.x;
    if (tid < 72) sw[tid] = w1[tid];
    __syncthreads();

    int p = blockIdx.x * 256 + tid;
    int b = blockIdx.y;
    float acc[8] = {0.f,0.f,0.f,0.f,0.f,0.f,0.f,0.f};
    if (p < HW) {
        int y = p / Ww, x = p - y * Ww;
        const float* src = d_dmr + b * HW;
        #pragma unroll
        for (int ky = 0; ky < 3; ky++) {
            int yy = y + ky - 1;
            if (yy < 0 || yy >= Hh) continue;
            #pragma unroll
            for (int kx = 0; kx < 3; kx++) {
                int xx = x + kx - 1;
                if (xx < 0 || xx >= Ww) continue;
                float v = src[yy * Ww + xx];
                int wi = ky * 3 + kx;
                #pragma unroll
                for (int c = 0; c < 8; c++) acc[c] = fmaf(v, sw[c * 9 + wi], acc[c]);
            }
        }
        float* dst = d_buf1 + (size_t)(b * 8) * HW + p;
        #pragma unroll
        for (int c = 0; c < 8; c++) dst[c * HW] = acc[c];
    }
    // deterministic fixed-tree stats: 16 quantities (sum, sumsq per channel)
    int lane = tid & 31, wid = tid >> 5;
    int blk = blockIdx.y * gridDim.x + blockIdx.x;
    #pragma unroll
    for (int q = 0; q < 16; q++) {
        int c = q >> 1;
        float v = (q & 1) ? acc[c] * acc[c] : acc[c];
        #pragma unroll
        for (int s = 16; s > 0; s >>= 1) v += __shfl_down_sync(0xffffffffu, v, s);
        if (lane == 0) wred[q * 8 + wid] = v;
    }
    __syncthreads();
    if (tid < 16) {
        float s = 0.f;
        #pragma unroll
        for (int w = 0; w < 8; w++) s += wred[tid * 8 + w];
        d_part1[tid * NB_TOT + blk] = s;
    }
}

__global__ void k_stats1(const float* __restrict__ g, const float* __restrict__ be) {
    int tid = threadIdx.x;
    __shared__ float sums[16];
    if (tid < 16) {
        float s = 0.f;
        for (int i = 0; i < NB_TOT; i++) s += d_part1[tid * NB_TOT + i];
        sums[tid] = s;
    }
    __syncthreads();
    if (tid < 8) {
        float mean = sums[tid * 2] / (float)CNT;
        float var  = sums[tid * 2 + 1] / (float)CNT - mean * mean;
        float inv  = rsqrtf(var + BN_EPS);
        float sc   = g[tid] * inv;
        d_sc1[tid] = sc;
        d_sh1[tid] = be[tid] - mean * sc;
    }
}

// bn1+relu applied on the fly, conv3x3 8->16 (zero pad on h), partial stats for BN2
__global__ void k_conv2(const float* __restrict__ w2) {
    __shared__ float sw[1152];
    __shared__ float ssc[8], ssh[8];
    __shared__ float wred[32 * 8];
    int tid = threadIdx.x;
    for (int i = tid; i < 1152; i += 256) sw[i] = w2[i];
    if (tid < 8) { ssc[tid] = d_sc1[tid]; ssh[tid] = d_sh1[tid]; }
    __syncthreads();

    int p = blockIdx.x * 256 + tid;
    int b = blockIdx.y;
    float acc[16];
    #pragma unroll
    for (int i = 0; i < 16; i++) acc[i] = 0.f;
    if (p < HW) {
        int y = p / Ww, x = p - y * Ww;
        const float* src = d_buf1 + (size_t)(b * 8) * HW;
        #pragma unroll
        for (int ky = 0; ky < 3; ky++) {
            int yy = y + ky - 1;
            if (yy < 0 || yy >= Hh) continue;
            #pragma unroll
            for (int kx = 0; kx < 3; kx++) {
                int xx = x + kx - 1;
                if (xx < 0 || xx >= Ww) continue;
                int off = yy * Ww + xx;
                int wi = ky * 3 + kx;
                float hbuf[8];
                #pragma unroll
                for (int c = 0; c < 8; c++) {
                    float v = src[c * HW + off];
                    hbuf[c] = fmaxf(fmaf(v, ssc[c], ssh[c]), 0.f);
                }
                #pragma unroll
                for (int oc = 0; oc < 16; oc++) {
                    #pragma unroll
                    for (int ic = 0; ic < 8; ic++)
                        acc[oc] = fmaf(hbuf[ic], sw[(oc * 8 + ic) * 9 + wi], acc[oc]);
                }
            }
        }
        float* dst = d_buf2 + (size_t)(b * 16) * HW + p;
        #pragma unroll
        for (int oc = 0; oc < 16; oc++) dst[oc * HW] = acc[oc];
    }
    int lane = tid & 31, wid = tid >> 5;
    int blk = blockIdx.y * gridDim.x + blockIdx.x;
    #pragma unroll
    for (int q = 0; q < 32; q++) {
        int c = q >> 1;
        float v = (q & 1) ? acc[c] * acc[c] : acc[c];
        #pragma unroll
        for (int s = 16; s > 0; s >>= 1) v += __shfl_down_sync(0xffffffffu, v, s);
        if (lane == 0) wred[q * 8 + wid] = v;
    }
    __syncthreads();
    if (tid < 32) {
        float s = 0.f;
        #pragma unroll
        for (int w = 0; w < 8; w++) s += wred[tid * 8 + w];
        d_part2[tid * NB_TOT + blk] = s;
    }
}

__global__ void k_stats2(const float* __restrict__ g, const float* __restrict__ be) {
    int tid = threadIdx.x;
    __shared__ float sums[32];
    if (tid < 32) {
        float s = 0.f;
        for (int i = 0; i < NB_TOT; i++) s += d_part2[tid * NB_TOT + i];
        sums[tid] = s;
    }
    __syncthreads();
    if (tid < 16) {
        float mean = sums[tid * 2] / (float)CNT;
        float var  = sums[tid * 2 + 1] / (float)CNT - mean * mean;
        float inv  = rsqrtf(var + BN_EPS);
        float sc   = g[tid] * inv;
        d_sc2[tid] = sc;
        d_sh2[tid] = be[tid] - mean * sc;
    }
}

// density channels: bn2+relu into out channels [384,400) — pipeline branch
__global__ __launch_bounds__(256) void k_dens(float4* __restrict__ out) {
    constexpr int N4 = Bb * NDF * PL4;    // 857088
    int i = blockIdx.x * 256 + threadIdx.x;
    if (i >= N4) return;
    int b = i / (NDF * PL4);
    int r = i - b * (NDF * PL4);
    int c = r / PL4;
    float4 v = reinterpret_cast<const float4*>(d_buf2)[i];
    float sc = d_sc2[c], sh = d_sh2[c];
    v.x = fmaxf(fmaf(v.x, sc, sh), 0.f);
    v.y = fmaxf(fmaf(v.y, sc, sh), 0.f);
    v.z = fmaxf(fmaf(v.z, sc, sh), 0.f);
    v.w = fmaxf(fmaf(v.w, sc, sh), 0.f);
    out[(size_t)b * BP4 + SP4 + r] = v;
}

// spatial passthrough into out channels [0,384) — copy branch, MLP=4
__global__ __launch_bounds__(256) void k_copy(const float4* __restrict__ sp,
                                              float4* __restrict__ out) {
    int base = blockIdx.x * 1024 + (int)threadIdx.x;
    int j0 = base, j1 = base + 256, j2 = base + 512, j3 = base + 768;
    float4 v0 = sp[j0];
    float4 v1 = sp[j1];
    float4 v2 = sp[j2];
    float4 v3 = sp[j3];
    int b0 = j0 / SP4, b1 = j1 / SP4, b2 = j2 / SP4, b3 = j3 / SP4;
    out[b0 * BP4 + (j0 - b0 * SP4)] = v0;
    out[b1 * BP4 + (j1 - b1 * SP4)] = v1;
    out[b2 * BP4 + (j2 - b2 * SP4)] = v2;
    out[b3 * BP4 + (j3 - b3 * SP4)] = v3;
}

// ---------------- launch: forked capture, pipeline at HIGH priority ----------
extern "C" void kernel_launch(void* const* d_in, const int* in_sizes, int n_in,
                              void* d_out, int out_size) {
    const float* spatial = (const float*)d_in[0];
    const float* points  = (const float*)d_in[1];
    const float* w1 = (const float*)d_in[2];
    const float* g1 = (const float*)d_in[3];
    const float* b1 = (const float*)d_in[4];
    const float* w2 = (const float*)d_in[5];
    const float* g2 = (const float*)d_in[6];
    const float* b2 = (const float*)d_in[7];
    float* out = (float*)d_out;
    const float4* sp4 = (const float4*)spatial;
    float4* out4 = (float4*)out;
    int npts = in_sizes[1] / 5;

    // high-priority pipeline stream + fork/join events; created once on the
    // first (non-capturing) call, reused in every subsequent call/capture
    static cudaStream_t sHi = nullptr;
    static cudaEvent_t eFork = nullptr, eJoin = nullptr;
    if (sHi == nullptr) {
        int loPrio = 0, hiPrio = 0;
        cudaDeviceGetStreamPriorityRange(&loPrio, &hiPrio);  // hiPrio = greatest
        cudaStreamCreateWithPriority(&sHi, cudaStreamNonBlocking, hiPrio);
        cudaEventCreateWithFlags(&eFork, cudaEventDisableTiming);
        cudaEventCreateWithFlags(&eJoin, cudaEventDisableTiming);
    }

    // fork: pipeline branch on high-priority stream
    cudaEventRecord(eFork, 0);
    cudaStreamWaitEvent(sHi, eFork, 0);

    k_init<<<512, 256, 0, sHi>>>();
    k_hist<<<(npts + 255) / 256, 256, 0, sHi>>>(points, npts);
    dim3 gb((NYNX + 255) / 256, Bb);
    k_vblur<<<gb, 256, 0, sHi>>>();
    k_hblur<<<gb, 256, 0, sHi>>>();
    dim3 gh(NBX, Bb);
    k_resize<<<gh, 256, 0, sHi>>>();
    k_conv1<<<gh, 256, 0, sHi>>>(w1);
    k_stats1<<<1, 64, 0, sHi>>>(g1, b1);
    k_conv2<<<gh, 256, 0, sHi>>>(w2);
    k_stats2<<<1, 64, 0, sHi>>>(g2, b2);
    k_dens<<<(Bb * NDF * PL4 + 255) / 256, 256, 0, sHi>>>(out4);
    cudaEventRecord(eJoin, sHi);

    // copy branch on the default-priority capture stream (bandwidth filler)
    static_assert(NCP % 1024 == 0, "copy grid");
    k_copy<<<NCP / 1024, 256>>>(sp4, out4);

    // join both branches before capture ends
    cudaStreamWaitEvent(0, eJoin, 0);
}